// round 10
// baseline (speedup 1.0000x reference)
#include <cuda_runtime.h>
#include <cstdint>

// ---------------------------------------------------------------------------
// MultiRectSDF: out[i] = min over 32 shapes of rotated-rect SDF at query[i].
//
// R9 = R8 structure + occupancy fix. R8 measured: regs=66 -> 3 blocks/SM
// (occ 32.6%), issue 70.2%, both pipes <52% => idle-issue bound, not pipe
// bound. __launch_bounds__(256, 4) caps regs at 64 -> 4 blocks/SM (~50% occ)
// to hide LDS latency and dep-chain gaps behind more warps.
//
// Math (unchanged, measured good):
//   minSq = min_i (relu(dx)^2 + relu(dy)^2),  minM = min_i max(dx,dy)
//   final = (minM < 0) ? minM : sqrt(minSq)
// Rotation via packed fma.rn.f32x2 (FFMA2); abs folded into scalar FADD;
// sqrt + inside/outside select hoisted out of the 32-shape loop.
// ---------------------------------------------------------------------------

static __device__ __forceinline__ unsigned long long pack2(float lo, float hi) {
    unsigned long long r;
    asm("mov.b64 %0, {%1, %2};" : "=l"(r) : "r"(__float_as_uint(lo)), "r"(__float_as_uint(hi)));
    return r;
}

static __device__ __forceinline__ void unpack2(unsigned long long v, float& lo, float& hi) {
    unsigned int a, b;
    asm("mov.b64 {%0, %1}, %2;" : "=r"(a), "=r"(b) : "l"(v));
    lo = __uint_as_float(a);
    hi = __uint_as_float(b);
}

static __device__ __forceinline__ unsigned long long ffma2(
    unsigned long long a, unsigned long long b, unsigned long long c) {
    unsigned long long d;
    asm("fma.rn.f32x2 %0, %1, %2, %3;" : "=l"(d) : "l"(a), "l"(b), "l"(c));
    return d;
}

static __device__ __forceinline__ float fsqrt_approx(float x) {
    float y;
    asm("sqrt.approx.f32 %0, %1;" : "=f"(y) : "f"(x));
    return y;
}

struct __align__(16) ShapeConst {
    unsigned long long cP, sP, nsP, ntxP, ntyP;  // duplicated packed (v,v)
    float nrx, nry;                              // negated half-extents
};  // 48 bytes -> 3x LDS.128 per shape

static constexpr int NSHAPES = 32;
static constexpr int PTS_PER_THREAD = 8;   // 2x float4 in, 4 packed pairs
static constexpr int BLOCK = 256;

__global__ __launch_bounds__(BLOCK, 4)   // cap 64 regs -> 4 blocks/SM
void multirect_sdf_fast(const float* __restrict__ query,
                        const float* __restrict__ trans,
                        const float* __restrict__ rads,
                        const float* __restrict__ angles,
                        float* __restrict__ out) {
    __shared__ ShapeConst sc[NSHAPES];

    if (threadIdx.x < NSHAPES) {
        const int i = threadIdx.x;
        float s, c;
        __sincosf(angles[i], &s, &c);   // |angle| <= 0.1 -> ~1e-7 abs error
        const float tx = trans[2 * i + 0];
        const float ty = trans[2 * i + 1];
        sc[i].cP   = pack2(c, c);
        sc[i].sP   = pack2(s, s);
        sc[i].nsP  = pack2(-s, -s);
        sc[i].ntxP = pack2(-tx, -tx);
        sc[i].ntyP = pack2(-ty, -ty);
        sc[i].nrx  = -rads[2 * i + 0];
        sc[i].nry  = -rads[2 * i + 1];
    }
    __syncthreads();

    const int tid = blockIdx.x * BLOCK + threadIdx.x;

    // 8 points = 4x float4 (layout: x0 y0 x1 y1 ...)
    const float4* q4 = reinterpret_cast<const float4*>(query);
    unsigned long long X[4], Y[4];
#pragma unroll
    for (int k = 0; k < 4; k++) {
        const float4 q = q4[tid * 4 + k];
        X[k] = pack2(q.x, q.z);
        Y[k] = pack2(q.y, q.w);
    }

    float minSq[PTS_PER_THREAD], minM[PTS_PER_THREAD];
#pragma unroll
    for (int p = 0; p < PTS_PER_THREAD; p++) {
        minSq[p] = 3.0e38f;
        minM[p]  = 3.0e38f;
    }

#pragma unroll 4
    for (int i = 0; i < NSHAPES; i++) {
        const ShapeConst k = sc[i];   // 3x LDS.128, amortized over 4 pairs
#pragma unroll
        for (int pr = 0; pr < 4; pr++) {
            // Packed rotation + translation: 4 FFMA2 per point-pair.
            const unsigned long long RX = ffma2(k.cP, X[pr], ffma2(k.nsP, Y[pr], k.ntxP));
            const unsigned long long RY = ffma2(k.sP, X[pr], ffma2(k.cP, Y[pr], k.ntyP));
            float rx0, rx1, ry0, ry1;
            unpack2(RX, rx0, rx1);
            unpack2(RY, ry0, ry1);

            {
                const float dx = fabsf(rx0) + k.nrx;     // FADD with |src|
                const float dy = fabsf(ry0) + k.nry;
                const float mx = fmaxf(dx, 0.0f);
                const float my = fmaxf(dy, 0.0f);
                const float sq = fmaf(mx, mx, my * my);
                minSq[2 * pr + 0] = fminf(minSq[2 * pr + 0], sq);
                minM[2 * pr + 0]  = fminf(minM[2 * pr + 0], fmaxf(dx, dy));
            }
            {
                const float dx = fabsf(rx1) + k.nrx;
                const float dy = fabsf(ry1) + k.nry;
                const float mx = fmaxf(dx, 0.0f);
                const float my = fmaxf(dy, 0.0f);
                const float sq = fmaf(mx, mx, my * my);
                minSq[2 * pr + 1] = fminf(minSq[2 * pr + 1], sq);
                minM[2 * pr + 1]  = fminf(minM[2 * pr + 1], fmaxf(dx, dy));
            }
        }
    }

    // Epilogue: sqrt + inside/outside select, once per point (amortized 32x).
    float res[PTS_PER_THREAD];
#pragma unroll
    for (int p = 0; p < PTS_PER_THREAD; p++) {
        const float o = fsqrt_approx(minSq[p]);   // sqrt(0) == 0 matches ref
        res[p] = (minM[p] < 0.0f) ? minM[p] : o;
    }

    float4* o4 = reinterpret_cast<float4*>(out);
    o4[tid * 2 + 0] = make_float4(res[0], res[1], res[2], res[3]);
    o4[tid * 2 + 1] = make_float4(res[4], res[5], res[6], res[7]);
}

// Generic fallback (any n, any shape count) — correctness safety net.
__global__ void multirect_sdf_generic(const float* __restrict__ query,
                                      const float* __restrict__ trans,
                                      const float* __restrict__ rads,
                                      const float* __restrict__ angles,
                                      float* __restrict__ out,
                                      int n, int ns) {
    const int i = blockIdx.x * blockDim.x + threadIdx.x;
    if (i >= n) return;
    const float qx = query[2 * i + 0];
    const float qy = query[2 * i + 1];
    float best = 3.0e38f;
    for (int s = 0; s < ns; s++) {
        float sn, c;
        __sincosf(angles[s], &sn, &c);
        const float rx = fmaf(c, qx, fmaf(-sn, qy, -trans[2 * s + 0]));
        const float ry = fmaf(sn, qx, fmaf(c, qy, -trans[2 * s + 1]));
        const float dx = fabsf(rx) - rads[2 * s + 0];
        const float dy = fabsf(ry) - rads[2 * s + 1];
        const float mx = fmaxf(dx, 0.0f);
        const float my = fmaxf(dy, 0.0f);
        const float o  = fsqrt_approx(fmaf(mx, mx, my * my));
        const float in = fminf(fmaxf(dx, dy), 0.0f);
        best = fminf(best, o + in);
    }
    out[i] = best;
}

extern "C" void kernel_launch(void* const* d_in, const int* in_sizes, int n_in,
                              void* d_out, int out_size) {
    const float* query  = (const float*)d_in[0];  // (N, 2) fp32
    const float* trans  = (const float*)d_in[1];  // (S, 2) fp32
    const float* rads   = (const float*)d_in[2];  // (S, 2) fp32
    const float* angles = (const float*)d_in[3];  // (S,)  fp32
    float* out = (float*)d_out;

    const int n  = in_sizes[0] / 2;
    const int ns = in_sizes[3];

    if (ns == NSHAPES && (n % PTS_PER_THREAD) == 0 &&
        ((n / PTS_PER_THREAD) % BLOCK) == 0) {
        const int threads = n / PTS_PER_THREAD;
        multirect_sdf_fast<<<threads / BLOCK, BLOCK>>>(query, trans, rads, angles, out);
    } else {
        const int blk = 256;
        multirect_sdf_generic<<<(n + blk - 1) / blk, blk>>>(query, trans, rads, angles,
                                                            out, n, ns);
    }
}

// round 11
// speedup vs baseline: 1.5180x; 1.5180x over previous
#include <cuda_runtime.h>
#include <cstdint>

// ---------------------------------------------------------------------------
// MultiRectSDF: out[i] = min over 32 shapes of rotated-rect SDF at query[i].
//
// R11 = R8 (best: 35.0us, regs 66) + occupancy via BLOCK GRANULARITY, not a
// reg cap. R9/R10 showed __launch_bounds__(256,4) makes ptxas rematerialize
// (+50% instructions, re-loads smem constants) -> 54us. Instead: 128-thread
// blocks pack 7 blocks/SM at 66 regs (28 warps, ~44% occ) vs 3x256 (24 warps).
// Also: unroll 8 (11KB body fits L1.5 I$, halves loop overhead), and a
// branch-free epilogue using minM<0 => minSq=0 => res = min(minM,0)+sqrt(minSq).
//
// Math (measured good since R5):
//   minSq = min_i (relu(dx)^2 + relu(dy)^2),  minM = min_i max(dx,dy)
// Rotation via packed fma.rn.f32x2 (FFMA2); abs folded into scalar FADD.
// ---------------------------------------------------------------------------

static __device__ __forceinline__ unsigned long long pack2(float lo, float hi) {
    unsigned long long r;
    asm("mov.b64 %0, {%1, %2};" : "=l"(r) : "r"(__float_as_uint(lo)), "r"(__float_as_uint(hi)));
    return r;
}

static __device__ __forceinline__ void unpack2(unsigned long long v, float& lo, float& hi) {
    unsigned int a, b;
    asm("mov.b64 {%0, %1}, %2;" : "=r"(a), "=r"(b) : "l"(v));
    lo = __uint_as_float(a);
    hi = __uint_as_float(b);
}

static __device__ __forceinline__ unsigned long long ffma2(
    unsigned long long a, unsigned long long b, unsigned long long c) {
    unsigned long long d;
    asm("fma.rn.f32x2 %0, %1, %2, %3;" : "=l"(d) : "l"(a), "l"(b), "l"(c));
    return d;
}

static __device__ __forceinline__ float fsqrt_approx(float x) {
    float y;
    asm("sqrt.approx.f32 %0, %1;" : "=f"(y) : "f"(x));
    return y;
}

struct __align__(16) ShapeConst {
    unsigned long long cP, sP, nsP, ntxP, ntyP;  // duplicated packed (v,v)
    float nrx, nry;                              // negated half-extents
};  // 48 bytes -> 3x LDS.128 per shape

static constexpr int NSHAPES = 32;
static constexpr int PTS_PER_THREAD = 8;   // 2x float4 in, 4 packed pairs
static constexpr int BLOCK = 128;          // finer occupancy quantization

__global__ __launch_bounds__(BLOCK)        // NO reg cap (R10 lesson)
void multirect_sdf_fast(const float* __restrict__ query,
                        const float* __restrict__ trans,
                        const float* __restrict__ rads,
                        const float* __restrict__ angles,
                        float* __restrict__ out) {
    __shared__ ShapeConst sc[NSHAPES];

    if (threadIdx.x < NSHAPES) {
        const int i = threadIdx.x;
        float s, c;
        __sincosf(angles[i], &s, &c);   // |angle| <= 0.1 -> ~1e-7 abs error
        const float tx = trans[2 * i + 0];
        const float ty = trans[2 * i + 1];
        sc[i].cP   = pack2(c, c);
        sc[i].sP   = pack2(s, s);
        sc[i].nsP  = pack2(-s, -s);
        sc[i].ntxP = pack2(-tx, -tx);
        sc[i].ntyP = pack2(-ty, -ty);
        sc[i].nrx  = -rads[2 * i + 0];
        sc[i].nry  = -rads[2 * i + 1];
    }
    __syncthreads();

    const int tid = blockIdx.x * BLOCK + threadIdx.x;

    // 8 points = 4x float4 (layout: x0 y0 x1 y1 ...)
    const float4* q4 = reinterpret_cast<const float4*>(query);
    unsigned long long X[4], Y[4];
#pragma unroll
    for (int k = 0; k < 4; k++) {
        const float4 q = q4[tid * 4 + k];
        X[k] = pack2(q.x, q.z);
        Y[k] = pack2(q.y, q.w);
    }

    float minSq[PTS_PER_THREAD], minM[PTS_PER_THREAD];
#pragma unroll
    for (int p = 0; p < PTS_PER_THREAD; p++) {
        minSq[p] = 3.0e38f;
        minM[p]  = 3.0e38f;
    }

#pragma unroll 8
    for (int i = 0; i < NSHAPES; i++) {
        const ShapeConst k = sc[i];   // 3x LDS.128, amortized over 4 pairs
#pragma unroll
        for (int pr = 0; pr < 4; pr++) {
            // Packed rotation + translation: 4 FFMA2 per point-pair.
            const unsigned long long RX = ffma2(k.cP, X[pr], ffma2(k.nsP, Y[pr], k.ntxP));
            const unsigned long long RY = ffma2(k.sP, X[pr], ffma2(k.cP, Y[pr], k.ntyP));
            float rx0, rx1, ry0, ry1;
            unpack2(RX, rx0, rx1);
            unpack2(RY, ry0, ry1);

            {
                const float dx = fabsf(rx0) + k.nrx;     // FADD with |src|
                const float dy = fabsf(ry0) + k.nry;
                const float mx = fmaxf(dx, 0.0f);
                const float my = fmaxf(dy, 0.0f);
                const float sq = fmaf(mx, mx, my * my);
                minSq[2 * pr + 0] = fminf(minSq[2 * pr + 0], sq);
                minM[2 * pr + 0]  = fminf(minM[2 * pr + 0], fmaxf(dx, dy));
            }
            {
                const float dx = fabsf(rx1) + k.nrx;
                const float dy = fabsf(ry1) + k.nry;
                const float mx = fmaxf(dx, 0.0f);
                const float my = fmaxf(dy, 0.0f);
                const float sq = fmaf(mx, mx, my * my);
                minSq[2 * pr + 1] = fminf(minSq[2 * pr + 1], sq);
                minM[2 * pr + 1]  = fminf(minM[2 * pr + 1], fmaxf(dx, dy));
            }
        }
    }

    // Branch-free epilogue: minM < 0 implies the inside shape contributed
    // sq = 0, so minSq = 0 and sqrt(minSq) = 0. Hence exactly:
    //   res = min(minM, 0) + sqrt(minSq)
    float res[PTS_PER_THREAD];
#pragma unroll
    for (int p = 0; p < PTS_PER_THREAD; p++) {
        res[p] = fminf(minM[p], 0.0f) + fsqrt_approx(minSq[p]);
    }

    float4* o4 = reinterpret_cast<float4*>(out);
    o4[tid * 2 + 0] = make_float4(res[0], res[1], res[2], res[3]);
    o4[tid * 2 + 1] = make_float4(res[4], res[5], res[6], res[7]);
}

// Generic fallback (any n, any shape count) — correctness safety net.
__global__ void multirect_sdf_generic(const float* __restrict__ query,
                                      const float* __restrict__ trans,
                                      const float* __restrict__ rads,
                                      const float* __restrict__ angles,
                                      float* __restrict__ out,
                                      int n, int ns) {
    const int i = blockIdx.x * blockDim.x + threadIdx.x;
    if (i >= n) return;
    const float qx = query[2 * i + 0];
    const float qy = query[2 * i + 1];
    float best = 3.0e38f;
    for (int s = 0; s < ns; s++) {
        float sn, c;
        __sincosf(angles[s], &sn, &c);
        const float rx = fmaf(c, qx, fmaf(-sn, qy, -trans[2 * s + 0]));
        const float ry = fmaf(sn, qx, fmaf(c, qy, -trans[2 * s + 1]));
        const float dx = fabsf(rx) - rads[2 * s + 0];
        const float dy = fabsf(ry) - rads[2 * s + 1];
        const float mx = fmaxf(dx, 0.0f);
        const float my = fmaxf(dy, 0.0f);
        const float o  = fsqrt_approx(fmaf(mx, mx, my * my));
        const float in = fminf(fmaxf(dx, dy), 0.0f);
        best = fminf(best, o + in);
    }
    out[i] = best;
}

extern "C" void kernel_launch(void* const* d_in, const int* in_sizes, int n_in,
                              void* d_out, int out_size) {
    const float* query  = (const float*)d_in[0];  // (N, 2) fp32
    const float* trans  = (const float*)d_in[1];  // (S, 2) fp32
    const float* rads   = (const float*)d_in[2];  // (S, 2) fp32
    const float* angles = (const float*)d_in[3];  // (S,)  fp32
    float* out = (float*)d_out;

    const int n  = in_sizes[0] / 2;
    const int ns = in_sizes[3];

    if (ns == NSHAPES && (n % PTS_PER_THREAD) == 0 &&
        ((n / PTS_PER_THREAD) % BLOCK) == 0) {
        const int threads = n / PTS_PER_THREAD;
        multirect_sdf_fast<<<threads / BLOCK, BLOCK>>>(query, trans, rads, angles, out);
    } else {
        const int blk = 256;
        multirect_sdf_generic<<<(n + blk - 1) / blk, blk>>>(query, trans, rads, angles,
                                                            out, n, ns);
    }
}